// round 4
// baseline (speedup 1.0000x reference)
#include <cuda_runtime.h>
#include <cstddef>

// Problem dims (fixed)
#define T_STEPS 128
#define BATCH   2048
#define IN0     18
#define H       256
#define G3      768   // 3*H
#define NB      16    // batch rows per block tile
#define NBT     8     // batch rows per thread
#define NBLK    (BATCH / NB)   // 128 blocks
#define NTHR    1024  // (kh, bh, j): kh = tid>>9, bh = (tid>>8)&1, j = tid&255

typedef unsigned long long u64;

// ---------------- scratch ----------------
__device__ float g_Wt_hh0[H * G3];   // transposed to [k][g]
__device__ float g_Wt_hh1[H * G3];
__device__ float g_Wt_ih1[H * G3];
__device__ float g_h2[BATCH * H];    // layer-1 final hidden, [b][c]

// ---------------- packed fp32x2 helpers ----------------
__device__ __forceinline__ u64 pk2(float a, float b) {
    u64 r; asm("mov.b64 %0, {%1, %2};" : "=l"(r) : "f"(a), "f"(b)); return r;
}
__device__ __forceinline__ void fma2(u64& d, u64 a, u64 b) {
    asm("fma.rn.f32x2 %0, %1, %2, %0;" : "+l"(d) : "l"(a), "l"(b));
}
__device__ __forceinline__ void add2(u64& d, u64 a) {
    asm("add.rn.f32x2 %0, %0, %1;" : "+l"(d) : "l"(a));
}
__device__ __forceinline__ float2 up2(u64 p) {
    float2 f; asm("mov.b64 {%0, %1}, %2;" : "=f"(f.x), "=f"(f.y) : "l"(p)); return f;
}
__device__ __forceinline__ float sigf(float x) {
    return __fdividef(1.f, 1.f + __expf(-x));
}
__device__ __forceinline__ float tanhf_fast(float x) {
    return 2.f * sigf(2.f * x) - 1.f;
}

// ---------------- transpose [768x256] -> [256x768] ----------------
__global__ void k_transpose(const float* __restrict__ src, int which) {
    float* dst = (which == 0) ? g_Wt_hh0 : (which == 1) ? g_Wt_hh1 : g_Wt_ih1;
    int idx = blockIdx.x * 256 + threadIdx.x;
    int k = idx / G3;
    int g = idx - k * G3;
    dst[idx] = src[g * H + k];
}

// ---- partial single-matrix gemm over k in [k0,k1) ----
__device__ __forceinline__ void gemm_part1(const float* __restrict__ Wt,
                                           const float* __restrict__ sbuf,
                                           u64* __restrict__ ar, u64* __restrict__ az,
                                           u64* __restrict__ an, int j, int k0, int k1) {
    const float* wp = Wt + (size_t)k0 * G3 + j;
    const float* hb = sbuf + k0 * NB;
#pragma unroll 4
    for (int k = k0; k < k1; k++) {
        float wr = __ldg(wp), wz = __ldg(wp + H), wn = __ldg(wp + 2 * H);
        u64 wr2 = pk2(wr, wr), wz2 = pk2(wz, wz), wn2 = pk2(wn, wn);
        const ulonglong2* hp = (const ulonglong2*)hb;
        ulonglong2 h0 = hp[0], h1v = hp[1];
        fma2(ar[0], h0.x, wr2);  fma2(ar[1], h0.y, wr2);
        fma2(az[0], h0.x, wz2);  fma2(az[1], h0.y, wz2);
        fma2(an[0], h0.x, wn2);  fma2(an[1], h0.y, wn2);
        fma2(ar[2], h1v.x, wr2); fma2(ar[3], h1v.y, wr2);
        fma2(az[2], h1v.x, wz2); fma2(az[3], h1v.y, wz2);
        fma2(an[2], h1v.x, wn2); fma2(an[3], h1v.y, wn2);
        wp += G3; hb += NB;
    }
}

// ---- partial dual gemm: input (Wti, sxb) + hidden (Wth, shb), k in [k0,k1) ----
__device__ __forceinline__ void gemm_part2(const float* __restrict__ Wti,
                                           const float* __restrict__ Wth,
                                           const float* __restrict__ sxb,
                                           const float* __restrict__ shb,
                                           u64* __restrict__ ar, u64* __restrict__ az,
                                           u64* __restrict__ axn, u64* __restrict__ ahn,
                                           int j, int k0, int k1) {
    const float* wpi = Wti + (size_t)k0 * G3 + j;
    const float* wph = Wth + (size_t)k0 * G3 + j;
    const float* xb = sxb + k0 * NB;
    const float* hb = shb + k0 * NB;
#pragma unroll 4
    for (int k = k0; k < k1; k++) {
        float wir = __ldg(wpi), wiz = __ldg(wpi + H), win = __ldg(wpi + 2 * H);
        float whr = __ldg(wph), whz = __ldg(wph + H), whn = __ldg(wph + 2 * H);
        u64 wir2 = pk2(wir, wir), wiz2 = pk2(wiz, wiz), win2 = pk2(win, win);
        u64 whr2 = pk2(whr, whr), whz2 = pk2(whz, whz), whn2 = pk2(whn, whn);
        const ulonglong2* xp = (const ulonglong2*)xb;
        const ulonglong2* hp = (const ulonglong2*)hb;
        ulonglong2 x0 = xp[0], x1 = xp[1];
        ulonglong2 h0 = hp[0], h1v = hp[1];
        fma2(ar[0], x0.x, wir2);  fma2(ar[1], x0.y, wir2);
        fma2(ar[2], x1.x, wir2);  fma2(ar[3], x1.y, wir2);
        fma2(az[0], x0.x, wiz2);  fma2(az[1], x0.y, wiz2);
        fma2(az[2], x1.x, wiz2);  fma2(az[3], x1.y, wiz2);
        fma2(axn[0], x0.x, win2); fma2(axn[1], x0.y, win2);
        fma2(axn[2], x1.x, win2); fma2(axn[3], x1.y, win2);
        fma2(ar[0], h0.x, whr2);  fma2(ar[1], h0.y, whr2);
        fma2(ar[2], h1v.x, whr2); fma2(ar[3], h1v.y, whr2);
        fma2(az[0], h0.x, whz2);  fma2(az[1], h0.y, whz2);
        fma2(az[2], h1v.x, whz2); fma2(az[3], h1v.y, whz2);
        fma2(ahn[0], h0.x, whn2); fma2(ahn[1], h0.y, whn2);
        fma2(ahn[2], h1v.x, whn2); fma2(ahn[3], h1v.y, whn2);
        wpi += G3; wph += G3; xb += NB; hb += NB;
    }
}

// store 16-u64 partial accumulator to exchange buffer (conflict-free layout)
__device__ __forceinline__ void red_store(ulonglong2* red, int low,
                                          const u64* ar, const u64* az,
                                          const u64* axn, const u64* ahn) {
    red[0 * 512 + low] = make_ulonglong2(ar[0], ar[1]);
    red[1 * 512 + low] = make_ulonglong2(ar[2], ar[3]);
    red[2 * 512 + low] = make_ulonglong2(az[0], az[1]);
    red[3 * 512 + low] = make_ulonglong2(az[2], az[3]);
    red[4 * 512 + low] = make_ulonglong2(axn[0], axn[1]);
    red[5 * 512 + low] = make_ulonglong2(axn[2], axn[3]);
    red[6 * 512 + low] = make_ulonglong2(ahn[0], ahn[1]);
    red[7 * 512 + low] = make_ulonglong2(ahn[2], ahn[3]);
}

__device__ __forceinline__ void red_add(const ulonglong2* red, int low,
                                        u64* ar, u64* az, u64* axn, u64* ahn) {
    ulonglong2 v;
    v = red[0 * 512 + low]; add2(ar[0], v.x);  add2(ar[1], v.y);
    v = red[1 * 512 + low]; add2(ar[2], v.x);  add2(ar[3], v.y);
    v = red[2 * 512 + low]; add2(az[0], v.x);  add2(az[1], v.y);
    v = red[3 * 512 + low]; add2(az[2], v.x);  add2(az[3], v.y);
    v = red[4 * 512 + low]; add2(axn[0], v.x); add2(axn[1], v.y);
    v = red[5 * 512 + low]; add2(axn[2], v.x); add2(axn[3], v.y);
    v = red[6 * 512 + low]; add2(ahn[0], v.x); add2(ahn[1], v.y);
    v = red[7 * 512 + low]; add2(ahn[2], v.x); add2(ahn[3], v.y);
}

// gates -> hnew[8]; old h read from smem slice (thread-private)
__device__ __forceinline__ void epilogue(u64* ar, u64* az, u64* axn, u64* ahn,
                                         const float* hold, float* hnew) {
#pragma unroll
    for (int p = 0; p < 4; p++) {
        float2 r2 = up2(ar[p]), z2 = up2(az[p]), x2 = up2(axn[p]), h2 = up2(ahn[p]);
        float r0 = sigf(r2.x), z0 = sigf(z2.x);
        float n0 = tanhf_fast(x2.x + r0 * h2.x);
        hnew[2 * p] = n0 + z0 * (hold[2 * p] - n0);
        float r1 = sigf(r2.y), z1 = sigf(z2.y);
        float n1 = tanhf_fast(x2.y + r1 * h2.y);
        hnew[2 * p + 1] = n1 + z1 * (hold[2 * p + 1] - n1);
    }
}

// ---------------- fused 2-layer GRU, k-split across thread halves ----------------
__global__ __launch_bounds__(NTHR, 1)
void k_gru(const float* __restrict__ x, const float* __restrict__ Wih0,
           const float* __restrict__ bih0, const float* __restrict__ bhh0,
           const float* __restrict__ bih1, const float* __restrict__ bhh1) {
    extern __shared__ float smem[];
    float* sWih = smem;                       // [i][g], 18*768 = 13824 floats
    float* sh0  = sWih + IN0 * G3;            // layer-0 h, [c][b], 4096 floats
    float* sh1  = sh0 + H * NB;               // layer-1 h, 4096 floats
    float* sx   = sh1 + H * NB;               // x tiles, ping-pong, 2*288 floats
    ulonglong2* red = (ulonglong2*)(sx + 2 * IN0 * NB);  // 8*512 ulonglong2 = 64KB

    const int tid = threadIdx.x;
    const int kh  = tid >> 9;        // k-half: 0 or 1
    const int low = tid & 511;
    const int j   = low & 255;
    const int bh  = low >> 8;
    const int bo  = bh * NBT;
    const int k0  = kh * (H / 2), k1 = k0 + (H / 2);
    const int bbase = blockIdx.x * NB;

    // stage W_ih0 transposed into smem
    for (int idx = tid; idx < IN0 * G3; idx += NTHR) {
        int i = idx / G3, g = idx - i * G3;
        sWih[idx] = Wih0[g * IN0 + i];
    }
    for (int idx = tid; idx < 2 * H * NB; idx += NTHR) sh0[idx] = 0.f;
    // stage x[0] tile into sx buffer 0
    for (int idx = tid; idx < IN0 * NB; idx += NTHR) {
        int b = idx / IN0, i = idx - b * IN0;
        sx[i * NB + b] = x[((size_t)bbase + b) * IN0 + i];
    }

    float brz0 = 0.f, bzz0 = 0.f, bxn0 = 0.f, bhn0 = 0.f;
    float brz1 = 0.f, bzz1 = 0.f, bxn1 = 0.f, bhn1 = 0.f;
    if (kh == 0) {
        brz0 = bih0[j] + bhh0[j];
        bzz0 = bih0[H + j] + bhh0[H + j];
        bxn0 = bih0[2 * H + j];
        bhn0 = bhh0[2 * H + j];
        brz1 = bih1[j] + bhh1[j];
        bzz1 = bih1[H + j] + bhh1[H + j];
        bxn1 = bih1[2 * H + j];
        bhn1 = bhh1[2 * H + j];
    }
    __syncthreads();

    float* myh0 = sh0 + j * NB + bo;
    float* myh1 = sh1 + j * NB + bo;

    for (int t = 0; t < T_STEPS; t++) {
        const float* sxc = sx + (t & 1) * (IN0 * NB) + bo;

        // ---------- layer 0 partial accumulation ----------
        u64 ar[4], az[4], axn[4], ahn[4];
#pragma unroll
        for (int p = 0; p < 4; p++) {
            ar[p]  = pk2(brz0, brz0);  az[p]  = pk2(bzz0, bzz0);
            axn[p] = pk2(bxn0, bxn0);  ahn[p] = pk2(bhn0, bhn0);
        }
        // input projection: kh=0 does i 0..8, kh=1 does i 9..17
        {
            const int i0 = kh * 9;
#pragma unroll
            for (int ii = 0; ii < 9; ii++) {
                const int i = i0 + ii;
                float wr = sWih[i * G3 + j];
                float wz = sWih[i * G3 + H + j];
                float wn = sWih[i * G3 + 2 * H + j];
                u64 wr2 = pk2(wr, wr), wz2 = pk2(wz, wz), wn2 = pk2(wn, wn);
                const ulonglong2* xp = (const ulonglong2*)(sxc + i * NB);
                ulonglong2 v0 = xp[0], v1 = xp[1];
                fma2(ar[0], v0.x, wr2);  fma2(ar[1], v0.y, wr2);
                fma2(az[0], v0.x, wz2);  fma2(az[1], v0.y, wz2);
                fma2(axn[0], v0.x, wn2); fma2(axn[1], v0.y, wn2);
                fma2(ar[2], v1.x, wr2);  fma2(ar[3], v1.y, wr2);
                fma2(az[2], v1.x, wz2);  fma2(az[3], v1.y, wz2);
                fma2(axn[2], v1.x, wn2); fma2(axn[3], v1.y, wn2);
            }
        }
        gemm_part1(g_Wt_hh0, sh0 + bo, ar, az, ahn, j, k0, k1);
        if (kh) red_store(red, low, ar, az, axn, ahn);
        __syncthreads();   // partials visible; all reads of sh0 done

        if (!kh) {
            red_add(red, low, ar, az, axn, ahn);
            float hnew[NBT];
            epilogue(ar, az, axn, ahn, myh0, hnew);
            ((float4*)myh0)[0] = make_float4(hnew[0], hnew[1], hnew[2], hnew[3]);
            ((float4*)myh0)[1] = make_float4(hnew[4], hnew[5], hnew[6], hnew[7]);
        } else if (t + 1 < T_STEPS) {
            // overlap: stage x[t+1] into the other sx buffer
            float* sxn = sx + ((t + 1) & 1) * (IN0 * NB);
            for (int idx = low; idx < IN0 * NB; idx += 512) {
                int b = idx / IN0, i = idx - b * IN0;
                sxn[i * NB + b] = x[((size_t)((t + 1) * BATCH) + bbase + b) * IN0 + i];
            }
        }
        __syncthreads();   // new sh0 ready

        // ---------- layer 1 partial accumulation ----------
#pragma unroll
        for (int p = 0; p < 4; p++) {
            ar[p]  = pk2(brz1, brz1);  az[p]  = pk2(bzz1, bzz1);
            axn[p] = pk2(bxn1, bxn1);  ahn[p] = pk2(bhn1, bhn1);
        }
        gemm_part2(g_Wt_ih1, g_Wt_hh1, sh0 + bo, sh1 + bo, ar, az, axn, ahn, j, k0, k1);
        if (kh) red_store(red, low, ar, az, axn, ahn);
        __syncthreads();   // partials visible; all reads of sh1 done

        if (!kh) {
            red_add(red, low, ar, az, axn, ahn);
            float hnew[NBT];
            epilogue(ar, az, axn, ahn, myh1, hnew);
            ((float4*)myh1)[0] = make_float4(hnew[0], hnew[1], hnew[2], hnew[3]);
            ((float4*)myh1)[1] = make_float4(hnew[4], hnew[5], hnew[6], hnew[7]);
            if (t == T_STEPS - 1) {
#pragma unroll
                for (int b = 0; b < NBT; b++)
                    g_h2[(size_t)(bbase + bo + b) * H + j] = hnew[b];
            }
        }
        __syncthreads();   // new sh1 visible before next step
    }
}

// ---------------- FC head ----------------
__global__ void k_fc(const float* __restrict__ fcw, const float* __restrict__ fcb,
                     float* __restrict__ out) {
    int warp = threadIdx.x >> 5, lane = threadIdx.x & 31;
    int row = blockIdx.x * 8 + warp;
    const float* h = &g_h2[(size_t)row * H];
    float a0 = 0.f, a1 = 0.f, a2 = 0.f, a3 = 0.f;
    for (int k = lane; k < H; k += 32) {
        float hv = h[k];
        a0 += hv * fcw[k];
        a1 += hv * fcw[H + k];
        a2 += hv * fcw[2 * H + k];
        a3 += hv * fcw[3 * H + k];
    }
#pragma unroll
    for (int off = 16; off; off >>= 1) {
        a0 += __shfl_xor_sync(0xffffffffu, a0, off);
        a1 += __shfl_xor_sync(0xffffffffu, a1, off);
        a2 += __shfl_xor_sync(0xffffffffu, a2, off);
        a3 += __shfl_xor_sync(0xffffffffu, a3, off);
    }
    if (lane == 0) {
        float l0 = a0 + fcb[0], l1 = a1 + fcb[1], l2 = a2 + fcb[2], l3 = a3 + fcb[3];
        out[row * 4 + 0] = 2.f / (1.f + expf(-l0)) - 1.f;
        out[row * 4 + 1] = 2.f / (1.f + expf(-l1)) - 1.f;
        out[row * 4 + 2] = 2.f / (1.f + expf(-l2)) - 1.f;
        out[row * 4 + 3] = 2.f / (1.f + expf(-l3)) - 1.f;
    }
}

extern "C" void kernel_launch(void* const* d_in, const int* in_sizes, int n_in,
                              void* d_out, int out_size) {
    const float* x    = (const float*)d_in[0];
    const float* Wih0 = (const float*)d_in[1];
    const float* Whh0 = (const float*)d_in[2];
    const float* bih0 = (const float*)d_in[3];
    const float* bhh0 = (const float*)d_in[4];
    const float* Wih1 = (const float*)d_in[5];
    const float* Whh1 = (const float*)d_in[6];
    const float* bih1 = (const float*)d_in[7];
    const float* bhh1 = (const float*)d_in[8];
    const float* fcw  = (const float*)d_in[9];
    const float* fcb  = (const float*)d_in[10];
    float* out = (float*)d_out;

    // floats: sWih 13824 + sh0 4096 + sh1 4096 + sx 576 = 22592 (= 90368 B, 16B aligned)
    // + red 65536 B  => 155904 B total
    const int gru_smem = (IN0 * G3 + 2 * H * NB + 2 * IN0 * NB) * (int)sizeof(float) + 65536;
    static int smem_set = 0;
    if (!smem_set) {
        cudaFuncSetAttribute(k_gru, cudaFuncAttributeMaxDynamicSharedMemorySize, gru_smem);
        smem_set = 1;
    }

    k_transpose<<<G3, 256>>>(Whh0, 0);
    k_transpose<<<G3, 256>>>(Whh1, 1);
    k_transpose<<<G3, 256>>>(Wih1, 2);
    k_gru<<<NBLK, NTHR, gru_smem>>>(x, Wih0, bih0, bhh0, bih1, bhh1);
    k_fc<<<BATCH / 8, 256>>>(fcw, fcb, out);
}

// round 5
// speedup vs baseline: 1.7750x; 1.7750x over previous
#include <cuda_runtime.h>
#include <cstddef>

// Problem dims (fixed)
#define T_STEPS 128
#define BATCH   2048
#define IN0     18
#define H       256
#define G3      768   // 3*H
#define NB      16    // batch rows per block tile
#define NBT     8     // batch rows per thread (NB/2)
#define NBLK    (BATCH / NB)   // 128 blocks
#define NTHR    512   // (bh, j): bh = tid>>8, j = tid&255

typedef unsigned long long u64;

// ---------------- scratch ----------------
// gate-packed transposed weights: [k][j][4] (r, z, n, pad) -> one LDG.128 per (k,j)
__device__ float4 g_W4_hh0[H * H];   // [k*256 + j]
__device__ float4 g_W4_hh1[H * H];
__device__ float4 g_W4_ih1[H * H];
__device__ float g_h2[BATCH * H];    // layer-1 final hidden, [b][c]

// ---------------- packed fp32x2 helpers ----------------
__device__ __forceinline__ u64 pk2(float a, float b) {
    u64 r; asm("mov.b64 %0, {%1, %2};" : "=l"(r) : "f"(a), "f"(b)); return r;
}
__device__ __forceinline__ void fma2(u64& d, u64 a, u64 b) {
    asm("fma.rn.f32x2 %0, %1, %2, %0;" : "+l"(d) : "l"(a), "l"(b));
}
__device__ __forceinline__ float2 up2(u64 p) {
    float2 f; asm("mov.b64 {%0, %1}, %2;" : "=f"(f.x), "=f"(f.y) : "l"(p)); return f;
}
__device__ __forceinline__ float sigf(float x) {
    return __fdividef(1.f, 1.f + __expf(-x));
}
__device__ __forceinline__ float tanhf_fast(float x) {
    return 2.f * sigf(2.f * x) - 1.f;
}

// ---------------- transpose [3H x H] -> packed [k][j][4] ----------------
__global__ void k_transpose(const float* __restrict__ src, int which) {
    float4* dstv = (which == 0) ? g_W4_hh0 : (which == 1) ? g_W4_hh1 : g_W4_ih1;
    float* dst = (float*)dstv;
    int idx = blockIdx.x * 256 + threadIdx.x;   // grid = 768 blocks -> H*768 threads
    int k = idx / G3;
    int rem = idx - k * G3;
    int g = rem >> 8;          // gate 0..2
    int j = rem & 255;
    dst[(k * 256 + j) * 4 + g] = src[(g * H + j) * H + k];
    if (g == 0) dst[(k * 256 + j) * 4 + 3] = 0.f;   // pad
}

// ---- pipelined single-matrix gemm (layer-0 hidden), chunk=4k double buffer ----
__device__ __forceinline__ void gemm_pipe1(const float4* __restrict__ W4,
                                           const float* __restrict__ sbuf,
                                           u64* __restrict__ ar, u64* __restrict__ az,
                                           u64* __restrict__ an, int j) {
    const float4* wp = W4 + j;     // stride per k = 256 float4
    float4 wb[2][4];
#pragma unroll
    for (int kk = 0; kk < 4; kk++) wb[0][kk] = __ldg(wp + kk * 256);
#pragma unroll 2
    for (int c = 0; c < H / 4; c++) {
        const int cur = c & 1, nxt = cur ^ 1;
        if (c + 1 < H / 4) {
#pragma unroll
            for (int kk = 0; kk < 4; kk++)
                wb[nxt][kk] = __ldg(wp + ((c + 1) * 4 + kk) * 256);
        }
#pragma unroll
        for (int kk = 0; kk < 4; kk++) {
            const int k = c * 4 + kk;
            float4 w = wb[cur][kk];
            u64 wr2 = pk2(w.x, w.x), wz2 = pk2(w.y, w.y), wn2 = pk2(w.z, w.z);
            const ulonglong2* hp = (const ulonglong2*)(sbuf + k * NB);
            ulonglong2 h0 = hp[0], h1v = hp[1];
            fma2(ar[0], h0.x, wr2);  fma2(ar[1], h0.y, wr2);
            fma2(az[0], h0.x, wz2);  fma2(az[1], h0.y, wz2);
            fma2(an[0], h0.x, wn2);  fma2(an[1], h0.y, wn2);
            fma2(ar[2], h1v.x, wr2); fma2(ar[3], h1v.y, wr2);
            fma2(az[2], h1v.x, wz2); fma2(az[3], h1v.y, wz2);
            fma2(an[2], h1v.x, wn2); fma2(an[3], h1v.y, wn2);
        }
    }
}

// ---- pipelined dual gemm (layer 1), chunk=2k double buffer ----
__device__ __forceinline__ void gemm_pipe2(const float4* __restrict__ W4i,
                                           const float4* __restrict__ W4h,
                                           const float* __restrict__ sxb,
                                           const float* __restrict__ shb,
                                           u64* __restrict__ ar, u64* __restrict__ az,
                                           u64* __restrict__ axn, u64* __restrict__ ahn,
                                           int j) {
    const float4* wpi = W4i + j;
    const float4* wph = W4h + j;
    float4 wb[2][2][2];   // [buf][kk][matrix: 0=input 1=hidden]
#pragma unroll
    for (int kk = 0; kk < 2; kk++) {
        wb[0][kk][0] = __ldg(wpi + kk * 256);
        wb[0][kk][1] = __ldg(wph + kk * 256);
    }
#pragma unroll 2
    for (int c = 0; c < H / 2; c++) {
        const int cur = c & 1, nxt = cur ^ 1;
        if (c + 1 < H / 2) {
#pragma unroll
            for (int kk = 0; kk < 2; kk++) {
                wb[nxt][kk][0] = __ldg(wpi + ((c + 1) * 2 + kk) * 256);
                wb[nxt][kk][1] = __ldg(wph + ((c + 1) * 2 + kk) * 256);
            }
        }
#pragma unroll
        for (int kk = 0; kk < 2; kk++) {
            const int k = c * 2 + kk;
            float4 wi = wb[cur][kk][0];
            float4 wh = wb[cur][kk][1];
            u64 wir2 = pk2(wi.x, wi.x), wiz2 = pk2(wi.y, wi.y), win2 = pk2(wi.z, wi.z);
            u64 whr2 = pk2(wh.x, wh.x), whz2 = pk2(wh.y, wh.y), whn2 = pk2(wh.z, wh.z);
            const ulonglong2* xp = (const ulonglong2*)(sxb + k * NB);
            const ulonglong2* hp = (const ulonglong2*)(shb + k * NB);
            ulonglong2 x0 = xp[0], x1 = xp[1];
            ulonglong2 h0 = hp[0], h1v = hp[1];
            fma2(ar[0], x0.x, wir2);  fma2(ar[1], x0.y, wir2);
            fma2(ar[2], x1.x, wir2);  fma2(ar[3], x1.y, wir2);
            fma2(az[0], x0.x, wiz2);  fma2(az[1], x0.y, wiz2);
            fma2(az[2], x1.x, wiz2);  fma2(az[3], x1.y, wiz2);
            fma2(axn[0], x0.x, win2); fma2(axn[1], x0.y, win2);
            fma2(axn[2], x1.x, win2); fma2(axn[3], x1.y, win2);
            fma2(ar[0], h0.x, whr2);  fma2(ar[1], h0.y, whr2);
            fma2(ar[2], h1v.x, whr2); fma2(ar[3], h1v.y, whr2);
            fma2(az[0], h0.x, whz2);  fma2(az[1], h0.y, whz2);
            fma2(az[2], h1v.x, whz2); fma2(az[3], h1v.y, whz2);
            fma2(ahn[0], h0.x, whn2); fma2(ahn[1], h0.y, whn2);
            fma2(ahn[2], h1v.x, whn2); fma2(ahn[3], h1v.y, whn2);
        }
    }
}

// gates -> hnew[8]; old h read from smem slice (thread-private)
__device__ __forceinline__ void epilogue(u64* ar, u64* az, u64* axn, u64* ahn,
                                         const float* hold, float* hnew) {
#pragma unroll
    for (int p = 0; p < 4; p++) {
        float2 r2 = up2(ar[p]), z2 = up2(az[p]), x2 = up2(axn[p]), h2 = up2(ahn[p]);
        float r0 = sigf(r2.x), z0 = sigf(z2.x);
        float n0 = tanhf_fast(x2.x + r0 * h2.x);
        hnew[2 * p] = n0 + z0 * (hold[2 * p] - n0);
        float r1 = sigf(r2.y), z1 = sigf(z2.y);
        float n1 = tanhf_fast(x2.y + r1 * h2.y);
        hnew[2 * p + 1] = n1 + z1 * (hold[2 * p + 1] - n1);
    }
}

// ---------------- fused 2-layer GRU, persistent per batch tile ----------------
__global__ __launch_bounds__(NTHR, 1)
void k_gru(const float* __restrict__ x, const float* __restrict__ Wih0,
           const float* __restrict__ bih0, const float* __restrict__ bhh0,
           const float* __restrict__ bih1, const float* __restrict__ bhh1) {
    extern __shared__ float smem[];
    float* sWih = smem;                    // [i][g], 18*768
    float* sh0  = smem + IN0 * G3;         // layer-0 h, [c][b], 256*16
    float* sh1  = sh0 + H * NB;            // layer-1 h, [c][b]
    float* sx   = sh1 + H * NB;            // x tile, [i][b], 18*16

    const int tid = threadIdx.x;
    const int j  = tid & 255;
    const int bh = tid >> 8;
    const int bo = bh * NBT;
    const int bbase = blockIdx.x * NB;

    for (int idx = tid; idx < IN0 * G3; idx += NTHR) {
        int i = idx / G3, g = idx - i * G3;
        sWih[idx] = Wih0[g * IN0 + i];
    }
    for (int idx = tid; idx < 2 * H * NB; idx += NTHR) sh0[idx] = 0.f;

    const float brz0 = bih0[j] + bhh0[j];
    const float bzz0 = bih0[H + j] + bhh0[H + j];
    const float bxn0 = bih0[2 * H + j];
    const float bhn0 = bhh0[2 * H + j];
    const float brz1 = bih1[j] + bhh1[j];
    const float bzz1 = bih1[H + j] + bhh1[H + j];
    const float bxn1 = bih1[2 * H + j];
    const float bhn1 = bhh1[2 * H + j];
    __syncthreads();

    float* myh0 = sh0 + j * NB + bo;
    float* myh1 = sh1 + j * NB + bo;

    for (int t = 0; t < T_STEPS; t++) {
        // stage x[t] tile, transposed to [i][b]
        for (int idx = tid; idx < IN0 * NB; idx += NTHR) {
            int b = idx / IN0, i = idx - b * IN0;
            sx[i * NB + b] = x[((size_t)(t * BATCH) + bbase + b) * IN0 + i];
        }
        __syncthreads();

        // ---------- layer 0 ----------
        u64 ar[4], az[4], axn[4], ahn[4];
#pragma unroll
        for (int p = 0; p < 4; p++) {
            ar[p] = pk2(brz0, brz0); az[p] = pk2(bzz0, bzz0);
            axn[p] = pk2(bxn0, bxn0); ahn[p] = pk2(bhn0, bhn0);
        }
        const float* sxo = sx + bo;
#pragma unroll
        for (int i = 0; i < IN0; i++) {
            float wr = sWih[i * G3 + j];
            float wz = sWih[i * G3 + H + j];
            float wn = sWih[i * G3 + 2 * H + j];
            u64 wr2 = pk2(wr, wr), wz2 = pk2(wz, wz), wn2 = pk2(wn, wn);
            const ulonglong2* xp = (const ulonglong2*)(sxo + i * NB);
            ulonglong2 v0 = xp[0], v1 = xp[1];
            fma2(ar[0], v0.x, wr2);  fma2(ar[1], v0.y, wr2);
            fma2(az[0], v0.x, wz2);  fma2(az[1], v0.y, wz2);
            fma2(axn[0], v0.x, wn2); fma2(axn[1], v0.y, wn2);
            fma2(ar[2], v1.x, wr2);  fma2(ar[3], v1.y, wr2);
            fma2(az[2], v1.x, wz2);  fma2(az[3], v1.y, wz2);
            fma2(axn[2], v1.x, wn2); fma2(axn[3], v1.y, wn2);
        }
        gemm_pipe1(g_W4_hh0, sh0 + bo, ar, az, ahn, j);
        __syncthreads();   // all warps done reading sh0

        {
            float hnew[NBT];
            epilogue(ar, az, axn, ahn, myh0, hnew);
            ((float4*)myh0)[0] = make_float4(hnew[0], hnew[1], hnew[2], hnew[3]);
            ((float4*)myh0)[1] = make_float4(hnew[4], hnew[5], hnew[6], hnew[7]);
        }
        __syncthreads();   // sh0 (= layer-1 input) ready

        // ---------- layer 1 ----------
#pragma unroll
        for (int p = 0; p < 4; p++) {
            ar[p] = pk2(brz1, brz1); az[p] = pk2(bzz1, bzz1);
            axn[p] = pk2(bxn1, bxn1); ahn[p] = pk2(bhn1, bhn1);
        }
        gemm_pipe2(g_W4_ih1, g_W4_hh1, sh0 + bo, sh1 + bo, ar, az, axn, ahn, j);
        __syncthreads();   // all warps done reading sh1

        {
            float hnew[NBT];
            epilogue(ar, az, axn, ahn, myh1, hnew);
            ((float4*)myh1)[0] = make_float4(hnew[0], hnew[1], hnew[2], hnew[3]);
            ((float4*)myh1)[1] = make_float4(hnew[4], hnew[5], hnew[6], hnew[7]);
            if (t == T_STEPS - 1) {
#pragma unroll
                for (int b = 0; b < NBT; b++)
                    g_h2[(size_t)(bbase + bo + b) * H + j] = hnew[b];
            }
        }
        __syncthreads();   // sh1 writes visible before next step's gemm
    }
}

// ---------------- FC head ----------------
__global__ void k_fc(const float* __restrict__ fcw, const float* __restrict__ fcb,
                     float* __restrict__ out) {
    int warp = threadIdx.x >> 5, lane = threadIdx.x & 31;
    int row = blockIdx.x * 8 + warp;
    const float* h = &g_h2[(size_t)row * H];
    float a0 = 0.f, a1 = 0.f, a2 = 0.f, a3 = 0.f;
    for (int k = lane; k < H; k += 32) {
        float hv = h[k];
        a0 += hv * fcw[k];
        a1 += hv * fcw[H + k];
        a2 += hv * fcw[2 * H + k];
        a3 += hv * fcw[3 * H + k];
    }
#pragma unroll
    for (int off = 16; off; off >>= 1) {
        a0 += __shfl_xor_sync(0xffffffffu, a0, off);
        a1 += __shfl_xor_sync(0xffffffffu, a1, off);
        a2 += __shfl_xor_sync(0xffffffffu, a2, off);
        a3 += __shfl_xor_sync(0xffffffffu, a3, off);
    }
    if (lane == 0) {
        float l0 = a0 + fcb[0], l1 = a1 + fcb[1], l2 = a2 + fcb[2], l3 = a3 + fcb[3];
        out[row * 4 + 0] = 2.f / (1.f + expf(-l0)) - 1.f;
        out[row * 4 + 1] = 2.f / (1.f + expf(-l1)) - 1.f;
        out[row * 4 + 2] = 2.f / (1.f + expf(-l2)) - 1.f;
        out[row * 4 + 3] = 2.f / (1.f + expf(-l3)) - 1.f;
    }
}

extern "C" void kernel_launch(void* const* d_in, const int* in_sizes, int n_in,
                              void* d_out, int out_size) {
    const float* x    = (const float*)d_in[0];
    const float* Wih0 = (const float*)d_in[1];
    const float* Whh0 = (const float*)d_in[2];
    const float* bih0 = (const float*)d_in[3];
    const float* bhh0 = (const float*)d_in[4];
    const float* Wih1 = (const float*)d_in[5];
    const float* Whh1 = (const float*)d_in[6];
    const float* bih1 = (const float*)d_in[7];
    const float* bhh1 = (const float*)d_in[8];
    const float* fcw  = (const float*)d_in[9];
    const float* fcb  = (const float*)d_in[10];
    float* out = (float*)d_out;

    const int gru_smem = (IN0 * G3 + 2 * H * NB + IN0 * NB) * (int)sizeof(float); // 89216 B
    static int smem_set = 0;
    if (!smem_set) {
        cudaFuncSetAttribute(k_gru, cudaFuncAttributeMaxDynamicSharedMemorySize, gru_smem);
        smem_set = 1;
    }

    k_transpose<<<G3, 256>>>(Whh0, 0);
    k_transpose<<<G3, 256>>>(Whh1, 1);
    k_transpose<<<G3, 256>>>(Wih1, 2);
    k_gru<<<NBLK, NTHR, gru_smem>>>(x, Wih0, bih0, bhh0, bih1, bhh1);
    k_fc<<<BATCH / 8, 256>>>(fcw, fcb, out);
}

// round 8
// speedup vs baseline: 1.9487x; 1.0979x over previous
#include <cuda_runtime.h>
#include <cstddef>

// Problem dims (fixed)
#define T_STEPS 128
#define BATCH   2048
#define IN0     18
#define H       256
#define G3      768   // 3*H
#define NB      16    // batch rows per block tile = rows per thread
#define NBLK    (BATCH / NB)   // 128 blocks
#define NTHR    256   // one thread per hidden unit j

typedef unsigned long long u64;

// ---------------- scratch ----------------
// gate-packed transposed weights: [k][j][4] (r, z, n, pad) -> one LDG.128 per (k,j)
__device__ float4 g_W4_hh0[H * H];   // [k*256 + j]
__device__ float4 g_W4_hh1[H * H];
__device__ float4 g_W4_ih1[H * H];
__device__ float g_h2[BATCH * H];    // layer-1 final hidden, [b][c]

// ---------------- packed fp32x2 helpers ----------------
__device__ __forceinline__ u64 pk2(float a, float b) {
    u64 r; asm("mov.b64 %0, {%1, %2};" : "=l"(r) : "f"(a), "f"(b)); return r;
}
__device__ __forceinline__ void fma2(u64& d, u64 a, u64 b) {
    asm("fma.rn.f32x2 %0, %1, %2, %0;" : "+l"(d) : "l"(a), "l"(b));
}
__device__ __forceinline__ float2 up2(u64 p) {
    float2 f; asm("mov.b64 {%0, %1}, %2;" : "=f"(f.x), "=f"(f.y) : "l"(p)); return f;
}
__device__ __forceinline__ float sigf(float x) {
    return __fdividef(1.f, 1.f + __expf(-x));
}
__device__ __forceinline__ float tanhf_fast(float x) {
    return 2.f * sigf(2.f * x) - 1.f;
}

// ---------------- transpose [3H x H] -> packed [k][j][4] ----------------
__global__ void k_transpose(const float* __restrict__ src, int which) {
    float4* dstv = (which == 0) ? g_W4_hh0 : (which == 1) ? g_W4_hh1 : g_W4_ih1;
    float* dst = (float*)dstv;
    int idx = blockIdx.x * 256 + threadIdx.x;   // grid = 768 blocks -> H*768 threads
    int k = idx / G3;
    int rem = idx - k * G3;
    int g = rem >> 8;          // gate 0..2
    int j = rem & 255;
    dst[(k * 256 + j) * 4 + g] = src[(g * H + j) * H + k];
    if (g == 0) dst[(k * 256 + j) * 4 + 3] = 0.f;   // pad
}

// fma a full 16-batch row (8 u64) against one gate weight into 8 accumulators
#define ROW_FMA(acc, wv)                                                     \
    do {                                                                     \
        fma2(acc[0], b0.x, wv); fma2(acc[1], b0.y, wv);                      \
        fma2(acc[2], b1.x, wv); fma2(acc[3], b1.y, wv);                      \
        fma2(acc[4], b2.x, wv); fma2(acc[5], b2.y, wv);                      \
        fma2(acc[6], b3.x, wv); fma2(acc[7], b3.y, wv);                      \
    } while (0)

// ---- pipelined single-matrix gemm (layer-0 hidden), chunk=4k double buffer ----
__device__ __forceinline__ void gemm_pipe1(const float4* __restrict__ W4,
                                           const float* __restrict__ sbuf,
                                           u64* __restrict__ ar, u64* __restrict__ az,
                                           u64* __restrict__ an, int j) {
    const float4* wp = W4 + j;     // stride per k = 256 float4
    float4 wb[2][4];
#pragma unroll
    for (int kk = 0; kk < 4; kk++) wb[0][kk] = __ldg(wp + kk * 256);
#pragma unroll 2
    for (int c = 0; c < H / 4; c++) {
        const int cur = c & 1, nxt = cur ^ 1;
        if (c + 1 < H / 4) {
#pragma unroll
            for (int kk = 0; kk < 4; kk++)
                wb[nxt][kk] = __ldg(wp + ((c + 1) * 4 + kk) * 256);
        }
#pragma unroll
        for (int kk = 0; kk < 4; kk++) {
            const int k = c * 4 + kk;
            float4 w = wb[cur][kk];
            u64 wr2 = pk2(w.x, w.x), wz2 = pk2(w.y, w.y), wn2 = pk2(w.z, w.z);
            const ulonglong2* hp = (const ulonglong2*)(sbuf + k * NB);
            ulonglong2 b0 = hp[0], b1 = hp[1], b2 = hp[2], b3 = hp[3];
            ROW_FMA(ar, wr2);
            ROW_FMA(az, wz2);
            ROW_FMA(an, wn2);
        }
    }
}

// ---- pipelined dual gemm (layer 1), chunk=2k double buffer ----
__device__ __forceinline__ void gemm_pipe2(const float4* __restrict__ W4i,
                                           const float4* __restrict__ W4h,
                                           const float* __restrict__ sxb,
                                           const float* __restrict__ shb,
                                           u64* __restrict__ ar, u64* __restrict__ az,
                                           u64* __restrict__ axn, u64* __restrict__ ahn,
                                           int j) {
    const float4* wpi = W4i + j;
    const float4* wph = W4h + j;
    float4 wb[2][2][2];   // [buf][kk][matrix: 0=input 1=hidden]
#pragma unroll
    for (int kk = 0; kk < 2; kk++) {
        wb[0][kk][0] = __ldg(wpi + kk * 256);
        wb[0][kk][1] = __ldg(wph + kk * 256);
    }
#pragma unroll 2
    for (int c = 0; c < H / 2; c++) {
        const int cur = c & 1, nxt = cur ^ 1;
        if (c + 1 < H / 2) {
#pragma unroll
            for (int kk = 0; kk < 2; kk++) {
                wb[nxt][kk][0] = __ldg(wpi + ((c + 1) * 2 + kk) * 256);
                wb[nxt][kk][1] = __ldg(wph + ((c + 1) * 2 + kk) * 256);
            }
        }
#pragma unroll
        for (int kk = 0; kk < 2; kk++) {
            const int k = c * 2 + kk;
            float4 wi = wb[cur][kk][0];
            float4 wh = wb[cur][kk][1];
            // input-side
            {
                u64 wr2 = pk2(wi.x, wi.x), wz2 = pk2(wi.y, wi.y), wn2 = pk2(wi.z, wi.z);
                const ulonglong2* xp = (const ulonglong2*)(sxb + k * NB);
                ulonglong2 b0 = xp[0], b1 = xp[1], b2 = xp[2], b3 = xp[3];
                ROW_FMA(ar, wr2);
                ROW_FMA(az, wz2);
                ROW_FMA(axn, wn2);
            }
            // hidden-side
            {
                u64 wr2 = pk2(wh.x, wh.x), wz2 = pk2(wh.y, wh.y), wn2 = pk2(wh.z, wh.z);
                const ulonglong2* hp = (const ulonglong2*)(shb + k * NB);
                ulonglong2 b0 = hp[0], b1 = hp[1], b2 = hp[2], b3 = hp[3];
                ROW_FMA(ar, wr2);
                ROW_FMA(az, wz2);
                ROW_FMA(ahn, wn2);
            }
        }
    }
}

// gates -> hnew[16]; old h read from smem slice (thread-private)
__device__ __forceinline__ void epilogue(u64* ar, u64* az, u64* axn, u64* ahn,
                                         const float* hold, float* hnew) {
#pragma unroll
    for (int p = 0; p < 8; p++) {
        float2 r2 = up2(ar[p]), z2 = up2(az[p]), x2 = up2(axn[p]), h2 = up2(ahn[p]);
        float r0 = sigf(r2.x), z0 = sigf(z2.x);
        float n0 = tanhf_fast(x2.x + r0 * h2.x);
        hnew[2 * p] = n0 + z0 * (hold[2 * p] - n0);
        float r1 = sigf(r2.y), z1 = sigf(z2.y);
        float n1 = tanhf_fast(x2.y + r1 * h2.y);
        hnew[2 * p + 1] = n1 + z1 * (hold[2 * p + 1] - n1);
    }
}

// ---------------- fused 2-layer GRU, persistent per batch tile ----------------
__global__ __launch_bounds__(NTHR, 1)
void k_gru(const float* __restrict__ x, const float* __restrict__ Wih0,
           const float* __restrict__ bih0, const float* __restrict__ bhh0,
           const float* __restrict__ bih1, const float* __restrict__ bhh1) {
    extern __shared__ float smem[];
    float* sWih = smem;                    // [i][g], 18*768
    float* sh0  = smem + IN0 * G3;         // layer-0 h, [c][b], 256*16
    float* sh1  = sh0 + H * NB;            // layer-1 h, [c][b]
    float* sx   = sh1 + H * NB;            // x tile, [i][b], 18*16

    const int j = threadIdx.x;
    const int bbase = blockIdx.x * NB;

    for (int idx = j; idx < IN0 * G3; idx += NTHR) {
        int i = idx / G3, g = idx - i * G3;
        sWih[idx] = Wih0[g * IN0 + i];
    }
    for (int idx = j; idx < 2 * H * NB; idx += NTHR) sh0[idx] = 0.f;

    const float brz0 = bih0[j] + bhh0[j];
    const float bzz0 = bih0[H + j] + bhh0[H + j];
    const float bxn0 = bih0[2 * H + j];
    const float bhn0 = bhh0[2 * H + j];
    const float brz1 = bih1[j] + bhh1[j];
    const float bzz1 = bih1[H + j] + bhh1[H + j];
    const float bxn1 = bih1[2 * H + j];
    const float bhn1 = bhh1[2 * H + j];
    __syncthreads();

    float* myh0 = sh0 + j * NB;
    float* myh1 = sh1 + j * NB;

    for (int t = 0; t < T_STEPS; t++) {
        // stage x[t] tile, transposed to [i][b]
        for (int idx = j; idx < IN0 * NB; idx += NTHR) {
            int b = idx / IN0, i = idx - b * IN0;
            sx[i * NB + b] = x[((size_t)(t * BATCH) + bbase + b) * IN0 + i];
        }
        __syncthreads();

        // ---------- layer 0 ----------
        u64 ar[8], az[8], axn[8], ahn[8];
#pragma unroll
        for (int p = 0; p < 8; p++) {
            ar[p] = pk2(brz0, brz0); az[p] = pk2(bzz0, bzz0);
            axn[p] = pk2(bxn0, bxn0); ahn[p] = pk2(bhn0, bhn0);
        }
        // input projection K=18 from smem
#pragma unroll
        for (int i = 0; i < IN0; i++) {
            float wr = sWih[i * G3 + j];
            float wz = sWih[i * G3 + H + j];
            float wn = sWih[i * G3 + 2 * H + j];
            u64 wr2 = pk2(wr, wr), wz2 = pk2(wz, wz), wn2 = pk2(wn, wn);
            const ulonglong2* xp = (const ulonglong2*)(sx + i * NB);
            ulonglong2 b0 = xp[0], b1 = xp[1], b2 = xp[2], b3 = xp[3];
            ROW_FMA(ar, wr2);
            ROW_FMA(az, wz2);
            ROW_FMA(axn, wn2);
        }
        gemm_pipe1(g_W4_hh0, sh0, ar, az, ahn, j);
        __syncthreads();   // all warps done reading sh0

        {
            float hnew[NB];
            epilogue(ar, az, axn, ahn, myh0, hnew);
#pragma unroll
            for (int q = 0; q < 4; q++)
                ((float4*)myh0)[q] = make_float4(hnew[4 * q], hnew[4 * q + 1],
                                                 hnew[4 * q + 2], hnew[4 * q + 3]);
        }
        __syncthreads();   // sh0 (= layer-1 input) ready

        // ---------- layer 1 ----------
#pragma unroll
        for (int p = 0; p < 8; p++) {
            ar[p] = pk2(brz1, brz1); az[p] = pk2(bzz1, bzz1);
            axn[p] = pk2(bxn1, bxn1); ahn[p] = pk2(bhn1, bhn1);
        }
        gemm_pipe2(g_W4_ih1, g_W4_hh1, sh0, sh1, ar, az, axn, ahn, j);
        __syncthreads();   // all warps done reading sh1

        {
            float hnew[NB];
            epilogue(ar, az, axn, ahn, myh1, hnew);
#pragma unroll
            for (int q = 0; q < 4; q++)
                ((float4*)myh1)[q] = make_float4(hnew[4 * q], hnew[4 * q + 1],
                                                 hnew[4 * q + 2], hnew[4 * q + 3]);
            if (t == T_STEPS - 1) {
#pragma unroll
                for (int b = 0; b < NB; b++)
                    g_h2[(size_t)(bbase + b) * H + j] = hnew[b];
            }
        }
        __syncthreads();   // sh1 writes visible before next step's gemm
    }
}

// ---------------- FC head ----------------
__global__ void k_fc(const float* __restrict__ fcw, const float* __restrict__ fcb,
                     float* __restrict__ out) {
    int warp = threadIdx.x >> 5, lane = threadIdx.x & 31;
    int row = blockIdx.x * 8 + warp;
    const float* h = &g_h2[(size_t)row * H];
    float a0 = 0.f, a1 = 0.f, a2 = 0.f, a3 = 0.f;
    for (int k = lane; k < H; k += 32) {
        float hv = h[k];
        a0 += hv * fcw[k];
        a1 += hv * fcw[H + k];
        a2 += hv * fcw[2 * H + k];
        a3 += hv * fcw[3 * H + k];
    }
#pragma unroll
    for (int off = 16; off; off >>= 1) {
        a0 += __shfl_xor_sync(0xffffffffu, a0, off);
        a1 += __shfl_xor_sync(0xffffffffu, a1, off);
        a2 += __shfl_xor_sync(0xffffffffu, a2, off);
        a3 += __shfl_xor_sync(0xffffffffu, a3, off);
    }
    if (lane == 0) {
        float l0 = a0 + fcb[0], l1 = a1 + fcb[1], l2 = a2 + fcb[2], l3 = a3 + fcb[3];
        out[row * 4 + 0] = 2.f / (1.f + expf(-l0)) - 1.f;
        out[row * 4 + 1] = 2.f / (1.f + expf(-l1)) - 1.f;
        out[row * 4 + 2] = 2.f / (1.f + expf(-l2)) - 1.f;
        out[row * 4 + 3] = 2.f / (1.f + expf(-l3)) - 1.f;
    }
}

extern "C" void kernel_launch(void* const* d_in, const int* in_sizes, int n_in,
                              void* d_out, int out_size) {
    const float* x    = (const float*)d_in[0];
    const float* Wih0 = (const float*)d_in[1];
    const float* Whh0 = (const float*)d_in[2];
    const float* bih0 = (const float*)d_in[3];
    const float* bhh0 = (const float*)d_in[4];
    const float* Wih1 = (const float*)d_in[5];
    const float* Whh1 = (const float*)d_in[6];
    const float* bih1 = (const float*)d_in[7];
    const float* bhh1 = (const float*)d_in[8];
    const float* fcw  = (const float*)d_in[9];
    const float* fcb  = (const float*)d_in[10];
    float* out = (float*)d_out;

    const int gru_smem = (IN0 * G3 + 2 * H * NB + IN0 * NB) * (int)sizeof(float); // 89216 B
    static int smem_set = 0;
    if (!smem_set) {
        cudaFuncSetAttribute(k_gru, cudaFuncAttributeMaxDynamicSharedMemorySize, gru_smem);
        smem_set = 1;
    }

    k_transpose<<<G3, 256>>>(Whh0, 0);
    k_transpose<<<G3, 256>>>(Whh1, 1);
    k_transpose<<<G3, 256>>>(Wih1, 2);
    k_gru<<<NBLK, NTHR, gru_smem>>>(x, Wih0, bih0, bhh0, bih1, bhh1);
    k_fc<<<BATCH / 8, 256>>>(fcw, fcb, out);
}

// round 9
// speedup vs baseline: 2.0138x; 1.0334x over previous
#include <cuda_runtime.h>
#include <cstddef>

// Problem dims (fixed)
#define T_STEPS 128
#define BATCH   2048
#define IN0     18
#define H       256
#define G3      768   // 3*H
#define NB      16    // batch rows per block tile = rows per thread
#define NBLK    (BATCH / NB)   // 128 blocks
#define NTHR    256   // one thread per hidden unit j

typedef unsigned long long u64;

// ---------------- scratch ----------------
// gate-packed transposed weights: [k][j][4] (r, z, n, pad) -> one LDG.128 per (k,j)
__device__ float4 g_W4_hh0[H * H];   // [k*256 + j]
__device__ float4 g_W4_hh1[H * H];
__device__ float4 g_W4_ih1[H * H];
__device__ float g_xT[(size_t)T_STEPS * NBLK * IN0 * NB];  // x pre-transposed [t][blk][i][b]
__device__ float g_h2[BATCH * H];    // layer-1 final hidden, [b][c]

// ---------------- packed fp32x2 helpers ----------------
__device__ __forceinline__ u64 pk2(float a, float b) {
    u64 r; asm("mov.b64 %0, {%1, %2};" : "=l"(r) : "f"(a), "f"(b)); return r;
}
__device__ __forceinline__ void fma2(u64& d, u64 a, u64 b) {
    asm("fma.rn.f32x2 %0, %1, %2, %0;" : "+l"(d) : "l"(a), "l"(b));
}
__device__ __forceinline__ float2 up2(u64 p) {
    float2 f; asm("mov.b64 {%0, %1}, %2;" : "=f"(f.x), "=f"(f.y) : "l"(p)); return f;
}
__device__ __forceinline__ float sigf(float x) {
    return __fdividef(1.f, 1.f + __expf(-x));
}
__device__ __forceinline__ float tanhf_fast(float x) {
    return 2.f * sigf(2.f * x) - 1.f;
}

// ---------------- transpose [3H x H] -> packed [k][j][4] ----------------
__global__ void k_transpose(const float* __restrict__ src, int which) {
    float4* dstv = (which == 0) ? g_W4_hh0 : (which == 1) ? g_W4_hh1 : g_W4_ih1;
    float* dst = (float*)dstv;
    int idx = blockIdx.x * 256 + threadIdx.x;   // grid = 768 blocks -> H*768 threads
    int k = idx / G3;
    int rem = idx - k * G3;
    int g = rem >> 8;          // gate 0..2
    int j = rem & 255;
    dst[(k * 256 + j) * 4 + g] = src[(g * H + j) * H + k];
    if (g == 0) dst[(k * 256 + j) * 4 + 3] = 0.f;   // pad
}

// ---------------- pre-transpose x: [t][b][i] -> [t][blk][i][b16] ----------------
__global__ void k_xt(const float* __restrict__ x) {
    size_t idx = (size_t)blockIdx.x * 1024 + threadIdx.x;   // coalesced read side
    if (idx >= (size_t)T_STEPS * BATCH * IN0) return;
    int i = (int)(idx % IN0);
    size_t tb = idx / IN0;
    int b = (int)(tb % BATCH);
    int t = (int)(tb / BATCH);
    int blk = b >> 4, b16 = b & 15;
    g_xT[(((size_t)t * NBLK + blk) * IN0 + i) * NB + b16] = x[idx];
}

// fma a full 16-batch row (8 u64) against one gate weight into 8 accumulators
#define ROW_FMA(acc, wv)                                                     \
    do {                                                                     \
        fma2(acc[0], b0.x, wv); fma2(acc[1], b0.y, wv);                      \
        fma2(acc[2], b1.x, wv); fma2(acc[3], b1.y, wv);                      \
        fma2(acc[4], b2.x, wv); fma2(acc[5], b2.y, wv);                      \
        fma2(acc[6], b3.x, wv); fma2(acc[7], b3.y, wv);                      \
    } while (0)

// ---- pipelined single-matrix gemm (layer-0 hidden), chunk=8k double buffer ----
__device__ __forceinline__ void gemm_pipe1(const float4* __restrict__ W4,
                                           const float* __restrict__ sbuf,
                                           u64* __restrict__ ar, u64* __restrict__ az,
                                           u64* __restrict__ an, int j) {
    const float4* wp = W4 + j;     // stride per k = 256 float4
    float4 wb[2][8];
#pragma unroll
    for (int kk = 0; kk < 8; kk++) wb[0][kk] = __ldg(wp + kk * 256);
#pragma unroll 2
    for (int c = 0; c < H / 8; c++) {
        const int cur = c & 1, nxt = cur ^ 1;
        if (c + 1 < H / 8) {
#pragma unroll
            for (int kk = 0; kk < 8; kk++)
                wb[nxt][kk] = __ldg(wp + ((c + 1) * 8 + kk) * 256);
        }
#pragma unroll
        for (int kk = 0; kk < 8; kk++) {
            const int k = c * 8 + kk;
            float4 w = wb[cur][kk];
            u64 wr2 = pk2(w.x, w.x), wz2 = pk2(w.y, w.y), wn2 = pk2(w.z, w.z);
            const ulonglong2* hp = (const ulonglong2*)(sbuf + k * NB);
            ulonglong2 b0 = hp[0], b1 = hp[1], b2 = hp[2], b3 = hp[3];
            ROW_FMA(ar, wr2);
            ROW_FMA(az, wz2);
            ROW_FMA(an, wn2);
        }
    }
}

// ---- pipelined dual gemm (layer 1), chunk=4k double buffer ----
__device__ __forceinline__ void gemm_pipe2(const float4* __restrict__ W4i,
                                           const float4* __restrict__ W4h,
                                           const float* __restrict__ sxb,
                                           const float* __restrict__ shb,
                                           u64* __restrict__ ar, u64* __restrict__ az,
                                           u64* __restrict__ axn, u64* __restrict__ ahn,
                                           int j) {
    const float4* wpi = W4i + j;
    const float4* wph = W4h + j;
    float4 wb[2][4][2];   // [buf][kk][matrix: 0=input 1=hidden]
#pragma unroll
    for (int kk = 0; kk < 4; kk++) {
        wb[0][kk][0] = __ldg(wpi + kk * 256);
        wb[0][kk][1] = __ldg(wph + kk * 256);
    }
#pragma unroll 2
    for (int c = 0; c < H / 4; c++) {
        const int cur = c & 1, nxt = cur ^ 1;
        if (c + 1 < H / 4) {
#pragma unroll
            for (int kk = 0; kk < 4; kk++) {
                wb[nxt][kk][0] = __ldg(wpi + ((c + 1) * 4 + kk) * 256);
                wb[nxt][kk][1] = __ldg(wph + ((c + 1) * 4 + kk) * 256);
            }
        }
#pragma unroll
        for (int kk = 0; kk < 4; kk++) {
            const int k = c * 4 + kk;
            float4 wi = wb[cur][kk][0];
            float4 wh = wb[cur][kk][1];
            // input-side
            {
                u64 wr2 = pk2(wi.x, wi.x), wz2 = pk2(wi.y, wi.y), wn2 = pk2(wi.z, wi.z);
                const ulonglong2* xp = (const ulonglong2*)(sxb + k * NB);
                ulonglong2 b0 = xp[0], b1 = xp[1], b2 = xp[2], b3 = xp[3];
                ROW_FMA(ar, wr2);
                ROW_FMA(az, wz2);
                ROW_FMA(axn, wn2);
            }
            // hidden-side
            {
                u64 wr2 = pk2(wh.x, wh.x), wz2 = pk2(wh.y, wh.y), wn2 = pk2(wh.z, wh.z);
                const ulonglong2* hp = (const ulonglong2*)(shb + k * NB);
                ulonglong2 b0 = hp[0], b1 = hp[1], b2 = hp[2], b3 = hp[3];
                ROW_FMA(ar, wr2);
                ROW_FMA(az, wz2);
                ROW_FMA(ahn, wn2);
            }
        }
    }
}

// gates -> hnew[16]; old h read from smem slice (thread-private)
__device__ __forceinline__ void epilogue(u64* ar, u64* az, u64* axn, u64* ahn,
                                         const float* hold, float* hnew) {
#pragma unroll
    for (int p = 0; p < 8; p++) {
        float2 r2 = up2(ar[p]), z2 = up2(az[p]), x2 = up2(axn[p]), h2 = up2(ahn[p]);
        float r0 = sigf(r2.x), z0 = sigf(z2.x);
        float n0 = tanhf_fast(x2.x + r0 * h2.x);
        hnew[2 * p] = n0 + z0 * (hold[2 * p] - n0);
        float r1 = sigf(r2.y), z1 = sigf(z2.y);
        float n1 = tanhf_fast(x2.y + r1 * h2.y);
        hnew[2 * p + 1] = n1 + z1 * (hold[2 * p + 1] - n1);
    }
}

// ---------------- fused 2-layer GRU, persistent per batch tile ----------------
// Double-buffered state -> only 2 __syncthreads per timestep.
__global__ __launch_bounds__(NTHR, 1)
void k_gru(const float* __restrict__ Wih0,
           const float* __restrict__ bih0, const float* __restrict__ bhh0,
           const float* __restrict__ bih1, const float* __restrict__ bhh1) {
    extern __shared__ float smem[];
    float* sWih = smem;                       // [i][g], 18*768 = 13824
    float* sh0  = sWih + IN0 * G3;            // layer-0 h, 2 bufs x [c][b] (4096 each)
    float* sh1  = sh0 + 2 * H * NB;           // layer-1 h, 2 bufs
    float* sx   = sh1 + 2 * H * NB;           // x tile, 2 bufs x [i][b] (288 each)

    const int j = threadIdx.x;
    const int bbase = blockIdx.x * NB;
    const size_t xtile = (size_t)IN0 * NB;

    for (int idx = j; idx < IN0 * G3; idx += NTHR) {
        int i = idx / G3, g = idx - i * G3;
        sWih[idx] = Wih0[g * IN0 + i];
    }
    // zero buffer 0 of both states
    for (int idx = j; idx < H * NB; idx += NTHR) {
        sh0[idx] = 0.f;
        sh1[idx] = 0.f;
    }
    // stage x[0] into sx buffer 0 (clean copy from pre-transposed g_xT)
    {
        const float4* src = (const float4*)(g_xT + ((size_t)0 * NBLK + blockIdx.x) * xtile);
        float4* dst = (float4*)sx;
        for (int idx = j; idx < IN0 * NB / 4; idx += NTHR) dst[idx] = src[idx];
    }

    const float brz0 = bih0[j] + bhh0[j];
    const float bzz0 = bih0[H + j] + bhh0[H + j];
    const float bxn0 = bih0[2 * H + j];
    const float bhn0 = bhh0[2 * H + j];
    const float brz1 = bih1[j] + bhh1[j];
    const float bzz1 = bih1[H + j] + bhh1[H + j];
    const float bxn1 = bih1[2 * H + j];
    const float bhn1 = bhh1[2 * H + j];
    __syncthreads();

    for (int t = 0; t < T_STEPS; t++) {
        const int tc = t & 1, tn = tc ^ 1;
        const float* sh0c = sh0 + tc * (H * NB);
        float*       sh0n = sh0 + tn * (H * NB);
        const float* sh1c = sh1 + tc * (H * NB);
        float*       sh1n = sh1 + tn * (H * NB);
        const float* sxc  = sx + tc * (IN0 * NB);

        // ---------- layer 0 ----------
        u64 ar[8], az[8], axn[8], ahn[8];
#pragma unroll
        for (int p = 0; p < 8; p++) {
            ar[p] = pk2(brz0, brz0); az[p] = pk2(bzz0, bzz0);
            axn[p] = pk2(bxn0, bxn0); ahn[p] = pk2(bhn0, bhn0);
        }
        // input projection K=18 from smem
#pragma unroll
        for (int i = 0; i < IN0; i++) {
            float wr = sWih[i * G3 + j];
            float wz = sWih[i * G3 + H + j];
            float wn = sWih[i * G3 + 2 * H + j];
            u64 wr2 = pk2(wr, wr), wz2 = pk2(wz, wz), wn2 = pk2(wn, wn);
            const ulonglong2* xp = (const ulonglong2*)(sxc + i * NB);
            ulonglong2 b0 = xp[0], b1 = xp[1], b2 = xp[2], b3 = xp[3];
            ROW_FMA(ar, wr2);
            ROW_FMA(az, wz2);
            ROW_FMA(axn, wn2);
        }
        gemm_pipe1(g_W4_hh0, sh0c, ar, az, ahn, j);

        // epilogue writes to the OTHER buffer -> no barrier needed before it
        {
            float hnew[NB];
            epilogue(ar, az, axn, ahn, sh0c + j * NB, hnew);
            float4* w = (float4*)(sh0n + j * NB);
#pragma unroll
            for (int q = 0; q < 4; q++)
                w[q] = make_float4(hnew[4 * q], hnew[4 * q + 1],
                                   hnew[4 * q + 2], hnew[4 * q + 3]);
        }
        // stage x[t+1] into the other sx buffer (overlaps with other warps' epilogue)
        if (t + 1 < T_STEPS) {
            const float4* src =
                (const float4*)(g_xT + ((size_t)(t + 1) * NBLK + blockIdx.x) * xtile);
            float4* dst = (float4*)(sx + tn * (IN0 * NB));
            for (int idx = j; idx < IN0 * NB / 4; idx += NTHR) dst[idx] = src[idx];
        }
        __syncthreads();   // B1: sh0[tn] + sx[tn] visible to all

        // ---------- layer 1 (input = NEW h0) ----------
#pragma unroll
        for (int p = 0; p < 8; p++) {
            ar[p] = pk2(brz1, brz1); az[p] = pk2(bzz1, bzz1);
            axn[p] = pk2(bxn1, bxn1); ahn[p] = pk2(bhn1, bhn1);
        }
        gemm_pipe2(g_W4_ih1, g_W4_hh1, sh0n, sh1c, ar, az, axn, ahn, j);

        {
            float hnew[NB];
            epilogue(ar, az, axn, ahn, sh1c + j * NB, hnew);
            float4* w = (float4*)(sh1n + j * NB);
#pragma unroll
            for (int q = 0; q < 4; q++)
                w[q] = make_float4(hnew[4 * q], hnew[4 * q + 1],
                                   hnew[4 * q + 2], hnew[4 * q + 3]);
            if (t == T_STEPS - 1) {
#pragma unroll
                for (int b = 0; b < NB; b++)
                    g_h2[(size_t)(bbase + b) * H + j] = hnew[b];
            }
        }
        __syncthreads();   // B2: sh1[tn] visible before next step
    }
}

// ---------------- FC head ----------------
__global__ void k_fc(const float* __restrict__ fcw, const float* __restrict__ fcb,
                     float* __restrict__ out) {
    int warp = threadIdx.x >> 5, lane = threadIdx.x & 31;
    int row = blockIdx.x * 8 + warp;
    const float* h = &g_h2[(size_t)row * H];
    float a0 = 0.f, a1 = 0.f, a2 = 0.f, a3 = 0.f;
    for (int k = lane; k < H; k += 32) {
        float hv = h[k];
        a0 += hv * fcw[k];
        a1 += hv * fcw[H + k];
        a2 += hv * fcw[2 * H + k];
        a3 += hv * fcw[3 * H + k];
    }
#pragma unroll
    for (int off = 16; off; off >>= 1) {
        a0 += __shfl_xor_sync(0xffffffffu, a0, off);
        a1 += __shfl_xor_sync(0xffffffffu, a1, off);
        a2 += __shfl_xor_sync(0xffffffffu, a2, off);
        a3 += __shfl_xor_sync(0xffffffffu, a3, off);
    }
    if (lane == 0) {
        float l0 = a0 + fcb[0], l1 = a1 + fcb[1], l2 = a2 + fcb[2], l3 = a3 + fcb[3];
        out[row * 4 + 0] = 2.f / (1.f + expf(-l0)) - 1.f;
        out[row * 4 + 1] = 2.f / (1.f + expf(-l1)) - 1.f;
        out[row * 4 + 2] = 2.f / (1.f + expf(-l2)) - 1.f;
        out[row * 4 + 3] = 2.f / (1.f + expf(-l3)) - 1.f;
    }
}

extern "C" void kernel_launch(void* const* d_in, const int* in_sizes, int n_in,
                              void* d_out, int out_size) {
    const float* x    = (const float*)d_in[0];
    const float* Wih0 = (const float*)d_in[1];
    const float* Whh0 = (const float*)d_in[2];
    const float* bih0 = (const float*)d_in[3];
    const float* bhh0 = (const float*)d_in[4];
    const float* Wih1 = (const float*)d_in[5];
    const float* Whh1 = (const float*)d_in[6];
    const float* bih1 = (const float*)d_in[7];
    const float* bhh1 = (const float*)d_in[8];
    const float* fcw  = (const float*)d_in[9];
    const float* fcb  = (const float*)d_in[10];
    float* out = (float*)d_out;

    // floats: sWih 13824 + sh0 8192 + sh1 8192 + sx 576 = 30784 -> 123136 B
    const int gru_smem = (IN0 * G3 + 4 * H * NB + 2 * IN0 * NB) * (int)sizeof(float);
    static int smem_set = 0;
    if (!smem_set) {
        cudaFuncSetAttribute(k_gru, cudaFuncAttributeMaxDynamicSharedMemorySize, gru_smem);
        smem_set = 1;
    }

    k_xt<<<(int)(((size_t)T_STEPS * BATCH * IN0 + 1023) / 1024), 1024>>>(x);
    k_transpose<<<G3, 256>>>(Whh0, 0);
    k_transpose<<<G3, 256>>>(Whh1, 1);
    k_transpose<<<G3, 256>>>(Wih1, 2);
    k_gru<<<NBLK, NTHR, gru_smem>>>(Wih0, bih0, bhh0, bih1, bhh1);
    k_fc<<<BATCH / 8, 256>>>(fcw, fcb, out);
}